// round 7
// baseline (speedup 1.0000x reference)
#include <cuda_runtime.h>
#include <math.h>

#define NND   50000
#define NE    800000
#define DIN   128
#define DH    64
#define DOUT  16
#define CAP   64
#define GRID  512
#define NTILE ((NND + 63) / 64)     // 782
#define NG    (NND / 8)             // 6250 (NND divisible by 8)

typedef unsigned long long ull;

__device__ __forceinline__ ull f2_pack2(float v) {
    ull r; asm("mov.b64 %0, {%1,%2};" : "=l"(r) : "f"(v), "f"(v)); return r;
}
__device__ __forceinline__ ull ffma2(ull a, ull b, ull c) {
    ull d; asm("fma.rn.f32x2 %0, %1, %2, %3;" : "=l"(d) : "l"(a), "l"(b), "l"(c)); return d;
}
__device__ __forceinline__ float2 f2_unpack(ull v) {
    float2 r; asm("mov.b64 {%0,%1}, %2;" : "=f"(r.x), "=f"(r.y) : "l"(v)); return r;
}

// ---------------- scratch ----------------
__device__ float g_h0[NND * DH];
__device__ float g_t1[NND * DH];
__device__ float g_t2[NND * DH];
__device__ float g_a2[NND * DH];
__device__ float g_t3[NND * DOUT];
__device__ int   g_cnt[NND];                  // statically zero; re-zeroed in phase 6
__device__ int2  g_slot[(size_t)NND * CAP];

// ---------------- grid barrier (replay-safe generation counter) ----------------
__device__ unsigned          g_count = 0;
__device__ volatile unsigned g_gen   = 0;

__device__ __forceinline__ void grid_sync() {
    __syncthreads();
    if (threadIdx.x == 0) {
        unsigned target = g_gen + 1;          // all blocks read same pre-release gen
        __threadfence();                      // release: publish phase writes
        if (atomicAdd(&g_count, 1u) == GRID - 1) {
            atomicExch(&g_count, 0u);         // reset for next barrier (L2-visible)
            __threadfence();
            g_gen = target;                   // release all
        } else {
            while (g_gen != target) { __nanosleep(32); }
        }
        __threadfence();                      // acquire
    }
    __syncthreads();
}

// ---------------- GEMM tile helpers (operate on shared xt[DH*66]) ----------------
// load 64 rows x 64 cols of src (row stride 'ld', col offset k0) transposed into xt
__device__ __forceinline__ void load_tile_T(float* xt, const float* __restrict__ src,
                                            int row0, int ld, int k0) {
    int tid = threadIdx.x;
    for (int i = tid; i < 64 * 16; i += 256) {
        int r = i >> 4, q = i & 15;
        int row = row0 + r;
        float4 v = (row < NND) ? *(const float4*)(src + (size_t)row * ld + k0 + q * 4)
                               : make_float4(0.f, 0.f, 0.f, 0.f);
        xt[(q * 4 + 0) * 66 + r] = v.x;
        xt[(q * 4 + 1) * 66 + r] = v.y;
        xt[(q * 4 + 2) * 66 + r] = v.z;
        xt[(q * 4 + 3) * 66 + r] = v.w;
    }
}

// ---------------- the single persistent kernel ----------------
__global__ void __launch_bounds__(256, 4)
gnn_persistent(const float* __restrict__ x,
               const int*   __restrict__ esrc,
               const int*   __restrict__ edst,
               const float* __restrict__ eval,
               const float* __restrict__ W1,
               const float* __restrict__ W2,
               const float* __restrict__ W3,
               float* __restrict__ out) {
    __shared__ float xt[DH * 66];             // 16.9 KB gemm tile
    __shared__ int2  se[8][CAP];              // 4 KB spmm edge stage
    int tid = threadIdx.x;
    int bid = blockIdx.x;
    int w = tid >> 5, lane = tid & 31;

    // ================= Phase 1: scatter + gemm1 (independent; overlap) =================
    for (int e = bid * 256 + tid; e < NE; e += GRID * 256) {
        int d = edst[e];
        int pos = atomicAdd(&g_cnt[d], 1);
        if (pos < CAP)
            g_slot[(size_t)d * CAP + pos] = make_int2(esrc[e], __float_as_int(eval[e]));
    }
    // gemm1: h0 = x @ W1, k split into two 64-chunks
    for (int t = bid; t < NTILE; t += GRID) {
        int row0 = t * 64;
        int c0 = (tid & 31) * 2;
        int rg = tid >> 5;
        ull acc[4][2] = {};
#pragma unroll
        for (int kc = 0; kc < 2; kc++) {
            __syncthreads();
            load_tile_T(xt, x, row0, DIN, kc * 64);
            __syncthreads();
            const float* xb = xt + rg * 8;
            for (int k = 0; k < 64; k++) {
                float2 wv = *(const float2*)(W1 + (size_t)(kc * 64 + k) * DH + c0);
                ull w0 = f2_pack2(wv.x), w1 = f2_pack2(wv.y);
                const float* xk = xb + k * 66;
#pragma unroll
                for (int p = 0; p < 4; p++) {
                    ull xp = *(const ull*)(xk + p * 2);
                    acc[p][0] = ffma2(xp, w0, acc[p][0]);
                    acc[p][1] = ffma2(xp, w1, acc[p][1]);
                }
            }
        }
#pragma unroll
        for (int p = 0; p < 4; p++) {
            float2 a0 = f2_unpack(acc[p][0]);
            float2 a1 = f2_unpack(acc[p][1]);
            int r0 = row0 + rg * 8 + p * 2;
            if (r0 < NND)     *(float2*)(g_h0 + (size_t)r0 * DH + c0)       = make_float2(a0.x, a1.x);
            if (r0 + 1 < NND) *(float2*)(g_h0 + (size_t)(r0 + 1) * DH + c0) = make_float2(a0.y, a1.y);
        }
    }
    grid_sync();

    // ================= Phase 2: t1 = tanh(A @ h0) =================
    for (int g = bid; g < NG; g += GRID) {
        int node = g * 8 + w;
        int deg = min(g_cnt[node], CAP);
        int degp = (deg + 7) & ~7;
        size_t base = (size_t)node * CAP;
        for (int i = lane; i < degp; i += 32)
            se[w][i] = (i < deg) ? g_slot[base + i] : make_int2(0, 0);
        __syncwarp();
        const char* pl = (const char*)g_h0 + ((size_t)lane << 3);
        ull acc0 = 0, acc1 = 0;
        for (int j = 0; j < degp; j += 8) {
            ull y[8], vv[8];
#pragma unroll
            for (int u = 0; u < 8; u++) {
                int2 e = se[w][j + u];
                y[u]  = *(const ull*)(pl + ((size_t)(unsigned)e.x << 8));
                vv[u] = f2_pack2(__int_as_float(e.y));
            }
#pragma unroll
            for (int u = 0; u < 8; u += 2) {
                acc0 = ffma2(y[u],     vv[u],     acc0);
                acc1 = ffma2(y[u + 1], vv[u + 1], acc1);
            }
        }
        float2 r0 = f2_unpack(acc0), r1 = f2_unpack(acc1);
        *(float2*)(g_t1 + ((size_t)node << 6) + (lane << 1)) =
            make_float2(tanhf(r0.x + r1.x), tanhf(r0.y + r1.y));
        __syncwarp();
    }
    grid_sync();

    // ================= Phase 3: t2 = t1 @ W2 =================
    for (int t = bid; t < NTILE; t += GRID) {
        int row0 = t * 64;
        __syncthreads();
        load_tile_T(xt, g_t1, row0, DH, 0);
        __syncthreads();
        int c0 = (tid & 31) * 2;
        int rg = tid >> 5;
        ull acc[4][2] = {};
        const float* xb = xt + rg * 8;
        for (int k = 0; k < DH; k++) {
            float2 wv = *(const float2*)(W2 + (size_t)k * DH + c0);
            ull w0 = f2_pack2(wv.x), w1 = f2_pack2(wv.y);
            const float* xk = xb + k * 66;
#pragma unroll
            for (int p = 0; p < 4; p++) {
                ull xp = *(const ull*)(xk + p * 2);
                acc[p][0] = ffma2(xp, w0, acc[p][0]);
                acc[p][1] = ffma2(xp, w1, acc[p][1]);
            }
        }
#pragma unroll
        for (int p = 0; p < 4; p++) {
            float2 a0 = f2_unpack(acc[p][0]);
            float2 a1 = f2_unpack(acc[p][1]);
            int r0 = row0 + rg * 8 + p * 2;
            if (r0 < NND)     *(float2*)(g_t2 + (size_t)r0 * DH + c0)       = make_float2(a0.x, a1.x);
            if (r0 + 1 < NND) *(float2*)(g_t2 + (size_t)(r0 + 1) * DH + c0) = make_float2(a0.y, a1.y);
        }
    }
    grid_sync();

    // ================= Phase 4: a2 = A @ t2 =================
    for (int g = bid; g < NG; g += GRID) {
        int node = g * 8 + w;
        int deg = min(g_cnt[node], CAP);
        int degp = (deg + 7) & ~7;
        size_t base = (size_t)node * CAP;
        for (int i = lane; i < degp; i += 32)
            se[w][i] = (i < deg) ? g_slot[base + i] : make_int2(0, 0);
        __syncwarp();
        const char* pl = (const char*)g_t2 + ((size_t)lane << 3);
        ull acc0 = 0, acc1 = 0;
        for (int j = 0; j < degp; j += 8) {
            ull y[8], vv[8];
#pragma unroll
            for (int u = 0; u < 8; u++) {
                int2 e = se[w][j + u];
                y[u]  = *(const ull*)(pl + ((size_t)(unsigned)e.x << 8));
                vv[u] = f2_pack2(__int_as_float(e.y));
            }
#pragma unroll
            for (int u = 0; u < 8; u += 2) {
                acc0 = ffma2(y[u],     vv[u],     acc0);
                acc1 = ffma2(y[u + 1], vv[u + 1], acc1);
            }
        }
        float2 r0 = f2_unpack(acc0), r1 = f2_unpack(acc1);
        *(float2*)(g_a2 + ((size_t)node << 6) + (lane << 1)) =
            make_float2(r0.x + r1.x, r0.y + r1.y);
        __syncwarp();
    }
    grid_sync();

    // ================= Phase 5: t3 = a2 @ W3 =================
    for (int t = bid; t < NTILE; t += GRID) {
        int row0 = t * 64;
        __syncthreads();
        load_tile_T(xt, g_a2, row0, DH, 0);
        __syncthreads();
        int c0 = (tid & 7) * 2;
        int rg = tid >> 3;
        ull acc0 = 0, acc1 = 0;
        const float* xb = xt + rg * 2;
        for (int k = 0; k < DH; k++) {
            float2 wv = *(const float2*)(W3 + (size_t)k * DOUT + c0);
            ull xp = *(const ull*)(xb + k * 66);
            acc0 = ffma2(xp, f2_pack2(wv.x), acc0);
            acc1 = ffma2(xp, f2_pack2(wv.y), acc1);
        }
        float2 a0 = f2_unpack(acc0);
        float2 a1 = f2_unpack(acc1);
        int r0 = row0 + rg * 2;
        if (r0 < NND)     *(float2*)(g_t3 + (size_t)r0 * DOUT + c0)       = make_float2(a0.x, a1.x);
        if (r0 + 1 < NND) *(float2*)(g_t3 + (size_t)(r0 + 1) * DOUT + c0) = make_float2(a0.y, a1.y);
    }
    grid_sync();

    // ================= Phase 6: out = softmax(A @ t3); reset cnt =================
    for (int g = bid; g < NG; g += GRID) {
        int node = g * 8 + w;
        int deg = min(g_cnt[node], CAP);
        if (lane == 0) g_cnt[node] = 0;       // restore invariant for next replay
        int degp = (deg + 7) & ~7;
        size_t base = (size_t)node * CAP;
        for (int i = lane; i < degp; i += 32)
            se[w][i] = (i < deg) ? g_slot[base + i] : make_int2(0, 0);
        __syncwarp();
        int half = lane >> 4, dim = lane & 15;
        const float* pl = g_t3 + dim;
        float acc = 0.f;
        for (int j = 0; j < degp; j += 8) {
            float y[4], v[4];
#pragma unroll
            for (int u = 0; u < 4; u++) {
                int2 e = se[w][j + u * 2 + half];
                y[u] = pl[(size_t)(unsigned)e.x * DOUT];
                v[u] = __int_as_float(e.y);
            }
#pragma unroll
            for (int u = 0; u < 4; u++) acc = fmaf(v[u], y[u], acc);
        }
        acc += __shfl_down_sync(0xffffffffu, acc, 16);
        float mx = acc;
#pragma unroll
        for (int o = 8; o > 0; o >>= 1)
            mx = fmaxf(mx, __shfl_xor_sync(0xffffffffu, mx, o));
        float e = expf(acc - mx);
        float s = e;
#pragma unroll
        for (int o = 8; o > 0; o >>= 1)
            s += __shfl_xor_sync(0xffffffffu, s, o);
        if (lane < DOUT)
            out[(size_t)node * DOUT + lane] = e / s;
        __syncwarp();
    }
}

// ---------------- launch: ONE kernel ----------------
extern "C" void kernel_launch(void* const* d_in, const int* in_sizes, int n_in,
                              void* d_out, int out_size) {
    const float* x    = (const float*)d_in[0];
    const int*   esrc = (const int*)  d_in[1];
    const int*   edst = (const int*)  d_in[2];
    const float* evals= (const float*)d_in[3];
    const float* W1   = (const float*)d_in[4];
    const float* W2   = (const float*)d_in[5];
    const float* W3   = (const float*)d_in[6];
    float* out = (float*)d_out;

    gnn_persistent<<<GRID, 256>>>(x, esrc, edst, evals, W1, W2, W3, out);
}

// round 8
// speedup vs baseline: 1.0945x; 1.0945x over previous
#include <cuda_runtime.h>
#include <math.h>

#define NND   50000
#define NE    800000
#define DIN   128
#define DH    64
#define DOUT  16
#define CAP   64
#define GRID  740                    // 148 SMs x 5 blocks, co-resident by __launch_bounds__
#define NT32  ((NND + 31) / 32)      // 1563 32-row gemm tiles
#define NG    (NND / 8)              // 6250 spmm warp-groups

typedef unsigned long long ull;

__device__ __forceinline__ ull f2_pack2(float v) {
    ull r; asm("mov.b64 %0, {%1,%2};" : "=l"(r) : "f"(v), "f"(v)); return r;
}
__device__ __forceinline__ ull ffma2(ull a, ull b, ull c) {
    ull d; asm("fma.rn.f32x2 %0, %1, %2, %3;" : "=l"(d) : "l"(a), "l"(b), "l"(c)); return d;
}
__device__ __forceinline__ float2 f2_unpack(ull v) {
    float2 r; asm("mov.b64 {%0,%1}, %2;" : "=f"(r.x), "=f"(r.y) : "l"(v)); return r;
}

// ---------------- scratch ----------------
__device__ float g_h0[NND * DH];
__device__ float g_t1[NND * DH];
__device__ float g_t2[NND * DH];
__device__ float g_a2[NND * DH];
__device__ float g_t3[NND * DOUT];
__device__ int   g_cnt[NND];                 // statically zero; re-zeroed in phase 6
__device__ int2  g_slot[(size_t)NND * CAP];
__device__ unsigned g_work[4];               // work-steal counters (gemm1/2/3); reset post-barrier

// ---------------- grid barrier (replay-safe generation counter) ----------------
__device__ unsigned          g_count = 0;
__device__ volatile unsigned g_gen   = 0;

__device__ __forceinline__ void grid_sync() {
    __syncthreads();
    if (threadIdx.x == 0) {
        unsigned target = g_gen + 1;
        __threadfence();
        if (atomicAdd(&g_count, 1u) == GRID - 1) {
            atomicExch(&g_count, 0u);
            __threadfence();
            g_gen = target;
        } else {
            while (g_gen != target) { __nanosleep(32); }
        }
        __threadfence();
    }
    __syncthreads();
}

// ---------------- the single persistent kernel ----------------
__global__ void __launch_bounds__(256, 5)
gnn_persistent(const float* __restrict__ x,
               const int*   __restrict__ esrc,
               const int*   __restrict__ edst,
               const float* __restrict__ eval,
               const float* __restrict__ W1,
               const float* __restrict__ W2,
               const float* __restrict__ W3,
               float* __restrict__ out) {
    __shared__ float xt[DIN * 34];            // 17.4 KB transposed gemm tile (pitch 34)
    __shared__ int2  se[8][CAP];              // 4 KB spmm edge stage
    __shared__ int   sh_tile;
    int tid = threadIdx.x;
    int bid = blockIdx.x;
    int w = tid >> 5, lane = tid & 31;

    // ================= Phase 1: scatter (strided) + gemm1 (work-steal) =================
    for (int e = bid * 256 + tid; e < NE; e += GRID * 256) {
        int d = edst[e];
        int pos = atomicAdd(&g_cnt[d], 1);
        if (pos < CAP)
            g_slot[(size_t)d * CAP + pos] = make_int2(esrc[e], __float_as_int(eval[e]));
    }
    for (;;) {
        __syncthreads();
        if (tid == 0) sh_tile = (int)atomicAdd(&g_work[0], 1u);
        __syncthreads();
        int t = sh_tile;
        if (t >= NT32) break;
        int row0 = t * 32;
        // load 32 rows x 128 cols transposed
        for (int i = tid; i < 32 * 32; i += 256) {
            int r = i >> 5, q = i & 31;
            int row = row0 + r;
            float4 v = (row < NND) ? *(const float4*)(x + (size_t)row * DIN + q * 4)
                                   : make_float4(0.f, 0.f, 0.f, 0.f);
            xt[(q * 4 + 0) * 34 + r] = v.x;
            xt[(q * 4 + 1) * 34 + r] = v.y;
            xt[(q * 4 + 2) * 34 + r] = v.z;
            xt[(q * 4 + 3) * 34 + r] = v.w;
        }
        __syncthreads();
        int c0 = (tid & 31) * 2;
        int rg = tid >> 5;                    // 8 groups x 4 rows
        ull acc[2][2] = {};
        for (int k = 0; k < DIN; k++) {
            float2 wv = *(const float2*)(W1 + (size_t)k * DH + c0);
            ull w0 = f2_pack2(wv.x), w1 = f2_pack2(wv.y);
            const float* xk = xt + k * 34 + rg * 4;
            ull xp0 = *(const ull*)(xk);
            ull xp1 = *(const ull*)(xk + 2);
            acc[0][0] = ffma2(xp0, w0, acc[0][0]);
            acc[0][1] = ffma2(xp0, w1, acc[0][1]);
            acc[1][0] = ffma2(xp1, w0, acc[1][0]);
            acc[1][1] = ffma2(xp1, w1, acc[1][1]);
        }
#pragma unroll
        for (int p = 0; p < 2; p++) {
            float2 a0 = f2_unpack(acc[p][0]);
            float2 a1 = f2_unpack(acc[p][1]);
            int r0 = row0 + rg * 4 + p * 2;
            if (r0 < NND)     *(float2*)(g_h0 + (size_t)r0 * DH + c0)       = make_float2(a0.x, a1.x);
            if (r0 + 1 < NND) *(float2*)(g_h0 + (size_t)(r0 + 1) * DH + c0) = make_float2(a0.y, a1.y);
        }
    }
    grid_sync();

    // ================= Phase 2: t1 = tanh(A @ h0) =================
    if (bid == 0 && tid == 0) g_work[0] = 0;   // reset gemm1 counter (post-barrier, replay-safe)
    for (int g = bid; g < NG; g += GRID) {
        int node = g * 8 + w;
        int deg = min(g_cnt[node], CAP);
        int degp = (deg + 7) & ~7;
        size_t base = (size_t)node * CAP;
        for (int i = lane; i < degp; i += 32)
            se[w][i] = (i < deg) ? g_slot[base + i] : make_int2(0, 0);
        __syncwarp();
        const char* pl = (const char*)g_h0 + ((size_t)lane << 3);
        ull acc0 = 0, acc1 = 0;
        for (int j = 0; j < degp; j += 8) {
            ull y[8], vv[8];
#pragma unroll
            for (int u = 0; u < 8; u++) {
                int2 e = se[w][j + u];
                y[u]  = *(const ull*)(pl + ((size_t)(unsigned)e.x << 8));
                vv[u] = f2_pack2(__int_as_float(e.y));
            }
#pragma unroll
            for (int u = 0; u < 8; u += 2) {
                acc0 = ffma2(y[u],     vv[u],     acc0);
                acc1 = ffma2(y[u + 1], vv[u + 1], acc1);
            }
        }
        float2 r0 = f2_unpack(acc0), r1 = f2_unpack(acc1);
        *(float2*)(g_t1 + ((size_t)node << 6) + (lane << 1)) =
            make_float2(tanhf(r0.x + r1.x), tanhf(r0.y + r1.y));
        __syncwarp();
    }
    grid_sync();

    // ================= Phase 3: t2 = t1 @ W2 (work-steal) =================
    for (;;) {
        __syncthreads();
        if (tid == 0) sh_tile = (int)atomicAdd(&g_work[1], 1u);
        __syncthreads();
        int t = sh_tile;
        if (t >= NT32) break;
        int row0 = t * 32;
        for (int i = tid; i < 32 * 16; i += 256) {
            int r = i >> 4, q = i & 15;
            int row = row0 + r;
            float4 v = (row < NND) ? *(const float4*)(g_t1 + (size_t)row * DH + q * 4)
                                   : make_float4(0.f, 0.f, 0.f, 0.f);
            xt[(q * 4 + 0) * 34 + r] = v.x;
            xt[(q * 4 + 1) * 34 + r] = v.y;
            xt[(q * 4 + 2) * 34 + r] = v.z;
            xt[(q * 4 + 3) * 34 + r] = v.w;
        }
        __syncthreads();
        int c0 = (tid & 31) * 2;
        int rg = tid >> 5;
        ull acc[2][2] = {};
        for (int k = 0; k < DH; k++) {
            float2 wv = *(const float2*)(W2 + (size_t)k * DH + c0);
            ull w0 = f2_pack2(wv.x), w1 = f2_pack2(wv.y);
            const float* xk = xt + k * 34 + rg * 4;
            ull xp0 = *(const ull*)(xk);
            ull xp1 = *(const ull*)(xk + 2);
            acc[0][0] = ffma2(xp0, w0, acc[0][0]);
            acc[0][1] = ffma2(xp0, w1, acc[0][1]);
            acc[1][0] = ffma2(xp1, w0, acc[1][0]);
            acc[1][1] = ffma2(xp1, w1, acc[1][1]);
        }
#pragma unroll
        for (int p = 0; p < 2; p++) {
            float2 a0 = f2_unpack(acc[p][0]);
            float2 a1 = f2_unpack(acc[p][1]);
            int r0 = row0 + rg * 4 + p * 2;
            if (r0 < NND)     *(float2*)(g_t2 + (size_t)r0 * DH + c0)       = make_float2(a0.x, a1.x);
            if (r0 + 1 < NND) *(float2*)(g_t2 + (size_t)(r0 + 1) * DH + c0) = make_float2(a0.y, a1.y);
        }
    }
    grid_sync();

    // ================= Phase 4: a2 = A @ t2 =================
    if (bid == 0 && tid == 0) g_work[1] = 0;
    for (int g = bid; g < NG; g += GRID) {
        int node = g * 8 + w;
        int deg = min(g_cnt[node], CAP);
        int degp = (deg + 7) & ~7;
        size_t base = (size_t)node * CAP;
        for (int i = lane; i < degp; i += 32)
            se[w][i] = (i < deg) ? g_slot[base + i] : make_int2(0, 0);
        __syncwarp();
        const char* pl = (const char*)g_t2 + ((size_t)lane << 3);
        ull acc0 = 0, acc1 = 0;
        for (int j = 0; j < degp; j += 8) {
            ull y[8], vv[8];
#pragma unroll
            for (int u = 0; u < 8; u++) {
                int2 e = se[w][j + u];
                y[u]  = *(const ull*)(pl + ((size_t)(unsigned)e.x << 8));
                vv[u] = f2_pack2(__int_as_float(e.y));
            }
#pragma unroll
            for (int u = 0; u < 8; u += 2) {
                acc0 = ffma2(y[u],     vv[u],     acc0);
                acc1 = ffma2(y[u + 1], vv[u + 1], acc1);
            }
        }
        float2 r0 = f2_unpack(acc0), r1 = f2_unpack(acc1);
        *(float2*)(g_a2 + ((size_t)node << 6) + (lane << 1)) =
            make_float2(r0.x + r1.x, r0.y + r1.y);
        __syncwarp();
    }
    grid_sync();

    // ================= Phase 5: t3 = a2 @ W3 (work-steal) =================
    for (;;) {
        __syncthreads();
        if (tid == 0) sh_tile = (int)atomicAdd(&g_work[2], 1u);
        __syncthreads();
        int t = sh_tile;
        if (t >= NT32) break;
        int row0 = t * 32;
        for (int i = tid; i < 32 * 16; i += 256) {
            int r = i >> 4, q = i & 15;
            int row = row0 + r;
            float4 v = (row < NND) ? *(const float4*)(g_a2 + (size_t)row * DH + q * 4)
                                   : make_float4(0.f, 0.f, 0.f, 0.f);
            xt[(q * 4 + 0) * 34 + r] = v.x;
            xt[(q * 4 + 1) * 34 + r] = v.y;
            xt[(q * 4 + 2) * 34 + r] = v.z;
            xt[(q * 4 + 3) * 34 + r] = v.w;
        }
        __syncthreads();
        int r = tid >> 3;                    // one row per thread
        int c0 = (tid & 7) * 2;              // one column pair
        ull acc = 0;
        for (int k = 0; k < DH; k++) {
            float2 wv = *(const float2*)(W3 + (size_t)k * DOUT + c0);
            ull wp; asm("mov.b64 %0, {%1,%2};" : "=l"(wp) : "f"(wv.x), "f"(wv.y));
            acc = ffma2(f2_pack2(xt[k * 34 + r]), wp, acc);
        }
        float2 a = f2_unpack(acc);
        int r0 = row0 + r;
        if (r0 < NND)
            *(float2*)(g_t3 + (size_t)r0 * DOUT + c0) = a;
    }
    grid_sync();

    // ================= Phase 6: out = softmax(A @ t3); reset cnt =================
    if (bid == 0 && tid == 0) g_work[2] = 0;
    for (int g = bid; g < NG; g += GRID) {
        int node = g * 8 + w;
        int deg = min(g_cnt[node], CAP);
        if (lane == 0) g_cnt[node] = 0;       // restore invariant for next replay
        int degp = (deg + 7) & ~7;
        size_t base = (size_t)node * CAP;
        for (int i = lane; i < degp; i += 32)
            se[w][i] = (i < deg) ? g_slot[base + i] : make_int2(0, 0);
        __syncwarp();
        int half = lane >> 4, dim = lane & 15;
        const float* pl = g_t3 + dim;
        float acc = 0.f;
        for (int j = 0; j < degp; j += 8) {
            float y[4], v[4];
#pragma unroll
            for (int u = 0; u < 4; u++) {
                int2 e = se[w][j + u * 2 + half];
                y[u] = pl[(size_t)(unsigned)e.x * DOUT];
                v[u] = __int_as_float(e.y);
            }
#pragma unroll
            for (int u = 0; u < 4; u++) acc = fmaf(v[u], y[u], acc);
        }
        acc += __shfl_down_sync(0xffffffffu, acc, 16);
        float mx = acc;
#pragma unroll
        for (int o = 8; o > 0; o >>= 1)
            mx = fmaxf(mx, __shfl_xor_sync(0xffffffffu, mx, o));
        float e = expf(acc - mx);
        float s = e;
#pragma unroll
        for (int o = 8; o > 0; o >>= 1)
            s += __shfl_xor_sync(0xffffffffu, s, o);
        if (lane < DOUT)
            out[(size_t)node * DOUT + lane] = e / s;
        __syncwarp();
    }
}

// ---------------- launch: ONE kernel ----------------
extern "C" void kernel_launch(void* const* d_in, const int* in_sizes, int n_in,
                              void* d_out, int out_size) {
    const float* x    = (const float*)d_in[0];
    const int*   esrc = (const int*)  d_in[1];
    const int*   edst = (const int*)  d_in[2];
    const float* evals= (const float*)d_in[3];
    const float* W1   = (const float*)d_in[4];
    const float* W2   = (const float*)d_in[5];
    const float* W3   = (const float*)d_in[6];
    float* out = (float*)d_out;

    gnn_persistent<<<GRID, 256>>>(x, esrc, edst, evals, W1, W2, W3, out);
}

// round 9
// speedup vs baseline: 1.4192x; 1.2967x over previous
#include <cuda_runtime.h>
#include <math.h>

#define NND   50000
#define NE    800000
#define DIN   128
#define DH    64
#define DOUT  16
#define CAP   64

typedef unsigned long long ull;

__device__ __forceinline__ ull f2_pack2(float v) {
    ull r; asm("mov.b64 %0, {%1,%2};" : "=l"(r) : "f"(v), "f"(v)); return r;
}
__device__ __forceinline__ ull ffma2(ull a, ull b, ull c) {
    ull d; asm("fma.rn.f32x2 %0, %1, %2, %3;" : "=l"(d) : "l"(a), "l"(b), "l"(c)); return d;
}
__device__ __forceinline__ float2 f2_unpack(ull v) {
    float2 r; asm("mov.b64 {%0,%1}, %2;" : "=f"(r.x), "=f"(r.y) : "l"(v)); return r;
}

// ---------------- scratch ----------------
__device__ float g_h0[NND * DH];
__device__ float g_t1[NND * DH];
__device__ float g_t2[NND * DH];
__device__ float g_a2[NND * DH];
__device__ float g_t3[NND * DOUT];
__device__ int   g_cnt[NND];            // statically zero; re-zeroed by final kernel each run
__device__ int2  g_slot[(size_t)NND * CAP];

// ---------------- scatter ----------------
__global__ void scatter_kernel(const int* __restrict__ esrc,
                               const int* __restrict__ edst,
                               const float* __restrict__ eval) {
    int e = blockIdx.x * 256 + threadIdx.x;
    if (e >= NE) return;
    int d = edst[e];
    int pos = atomicAdd(&g_cnt[d], 1);
    if (pos < CAP)
        g_slot[(size_t)d * CAP + pos] = make_int2(esrc[e], __float_as_int(eval[e]));
}

// ---------------- GEMM1: g_h0 = x @ W1   [N,128]x[128,64] ----------------
__global__ void gemm1_kernel(const float* __restrict__ x,
                             const float* __restrict__ W1) {
    __shared__ float xt[DIN * 66];
    int tid = threadIdx.x;
    int row0 = blockIdx.x * 64;
    for (int i = tid; i < 64 * (DIN / 4); i += 256) {
        int r = i >> 5, q = i & 31;
        int row = row0 + r;
        float4 v = (row < NND) ? *(const float4*)(x + (size_t)row * DIN + q * 4)
                               : make_float4(0.f, 0.f, 0.f, 0.f);
        xt[(q * 4 + 0) * 66 + r] = v.x;
        xt[(q * 4 + 1) * 66 + r] = v.y;
        xt[(q * 4 + 2) * 66 + r] = v.z;
        xt[(q * 4 + 3) * 66 + r] = v.w;
    }
    __syncthreads();
    int c0 = (tid & 31) * 2;
    int rg = tid >> 5;
    ull acc[4][2] = {};
    const float* xb = xt + rg * 8;
    for (int k = 0; k < DIN; k++) {
        float2 w = *(const float2*)(W1 + k * DH + c0);
        ull w0 = f2_pack2(w.x), w1 = f2_pack2(w.y);
        const float* xk = xb + k * 66;
#pragma unroll
        for (int p = 0; p < 4; p++) {
            ull xp = *(const ull*)(xk + p * 2);
            acc[p][0] = ffma2(xp, w0, acc[p][0]);
            acc[p][1] = ffma2(xp, w1, acc[p][1]);
        }
    }
#pragma unroll
    for (int p = 0; p < 4; p++) {
        float2 a0 = f2_unpack(acc[p][0]);
        float2 a1 = f2_unpack(acc[p][1]);
        int r0 = row0 + rg * 8 + p * 2;
        if (r0 < NND)     *(float2*)(g_h0 + (size_t)r0 * DH + c0)       = make_float2(a0.x, a1.x);
        if (r0 + 1 < NND) *(float2*)(g_h0 + (size_t)(r0 + 1) * DH + c0) = make_float2(a0.y, a1.y);
    }
}

// ---------------- GEMM2: g_t2 = g_t1 @ W2  [N,64]x[64,64] ----------------
__global__ void gemm2_kernel(const float* __restrict__ W2) {
    __shared__ float xt[DH * 66];
    int tid = threadIdx.x;
    int row0 = blockIdx.x * 64;
    for (int i = tid; i < 64 * (DH / 4); i += 256) {
        int r = i >> 4, q = i & 15;
        int row = row0 + r;
        float4 v = (row < NND) ? *(const float4*)(g_t1 + (size_t)row * DH + q * 4)
                               : make_float4(0.f, 0.f, 0.f, 0.f);
        xt[(q * 4 + 0) * 66 + r] = v.x;
        xt[(q * 4 + 1) * 66 + r] = v.y;
        xt[(q * 4 + 2) * 66 + r] = v.z;
        xt[(q * 4 + 3) * 66 + r] = v.w;
    }
    __syncthreads();
    int c0 = (tid & 31) * 2;
    int rg = tid >> 5;
    ull acc[4][2] = {};
    const float* xb = xt + rg * 8;
    for (int k = 0; k < DH; k++) {
        float2 w = *(const float2*)(W2 + k * DH + c0);
        ull w0 = f2_pack2(w.x), w1 = f2_pack2(w.y);
        const float* xk = xb + k * 66;
#pragma unroll
        for (int p = 0; p < 4; p++) {
            ull xp = *(const ull*)(xk + p * 2);
            acc[p][0] = ffma2(xp, w0, acc[p][0]);
            acc[p][1] = ffma2(xp, w1, acc[p][1]);
        }
    }
#pragma unroll
    for (int p = 0; p < 4; p++) {
        float2 a0 = f2_unpack(acc[p][0]);
        float2 a1 = f2_unpack(acc[p][1]);
        int r0 = row0 + rg * 8 + p * 2;
        if (r0 < NND)     *(float2*)(g_t2 + (size_t)r0 * DH + c0)       = make_float2(a0.x, a1.x);
        if (r0 + 1 < NND) *(float2*)(g_t2 + (size_t)(r0 + 1) * DH + c0) = make_float2(a0.y, a1.y);
    }
}

// ---------------- GEMM3: g_t3 = g_a2 @ W3  [N,64]x[64,16] ----------------
__global__ void gemm3_kernel(const float* __restrict__ W3) {
    __shared__ float xt[DH * 66];
    int tid = threadIdx.x;
    int row0 = blockIdx.x * 64;
    for (int i = tid; i < 64 * (DH / 4); i += 256) {
        int r = i >> 4, q = i & 15;
        int row = row0 + r;
        float4 v = (row < NND) ? *(const float4*)(g_a2 + (size_t)row * DH + q * 4)
                               : make_float4(0.f, 0.f, 0.f, 0.f);
        xt[(q * 4 + 0) * 66 + r] = v.x;
        xt[(q * 4 + 1) * 66 + r] = v.y;
        xt[(q * 4 + 2) * 66 + r] = v.z;
        xt[(q * 4 + 3) * 66 + r] = v.w;
    }
    __syncthreads();
    int c0 = (tid & 7) * 2;
    int rg = tid >> 3;
    ull acc0 = 0, acc1 = 0;
    const float* xb = xt + rg * 2;
    for (int k = 0; k < DH; k++) {
        float2 w = *(const float2*)(W3 + k * DOUT + c0);
        ull xp = *(const ull*)(xb + k * 66);
        acc0 = ffma2(xp, f2_pack2(w.x), acc0);
        acc1 = ffma2(xp, f2_pack2(w.y), acc1);
    }
    float2 a0 = f2_unpack(acc0);
    float2 a1 = f2_unpack(acc1);
    int r0 = row0 + rg * 2;
    if (r0 < NND)     *(float2*)(g_t3 + (size_t)r0 * DOUT + c0)       = make_float2(a0.x, a1.x);
    if (r0 + 1 < NND) *(float2*)(g_t3 + (size_t)(r0 + 1) * DOUT + c0) = make_float2(a0.y, a1.y);
}

// ---------------- SPMM 64-dim: 16-wide gather bursts, split stage (src / packed val) ----------------
// WHICH=0: g_h0 -> tanh -> g_t1 ;  WHICH=1: g_t2 -> g_a2
template <int WHICH>
__global__ void spmm64_kernel() {
    __shared__ int ss[8][CAP];        // edge src
    __shared__ ull sv[8][CAP];        // edge val pre-packed f32x2  (6 KB total)
    int w = threadIdx.x >> 5, lane = threadIdx.x & 31;
    int node = blockIdx.x * 8 + w;
    if (node >= NND) return;
    const float* __restrict__ hin = WHICH ? g_t2 : g_h0;
    float* __restrict__ hout      = WHICH ? g_a2 : g_t1;
    int deg = min(g_cnt[node], CAP);
    int degp = (deg + 15) & ~15;               // pad to multiple of 16
    size_t base = (size_t)node * CAP;
    for (int i = lane; i < degp; i += 32) {
        if (i < deg) {
            int2 e = g_slot[base + i];
            ss[w][i] = e.x;
            sv[w][i] = f2_pack2(__int_as_float(e.y));
        } else {
            ss[w][i] = 0;
            sv[w][i] = 0ull;
        }
    }
    __syncwarp();
    const char* pl = (const char*)hin + ((size_t)lane << 3);
    ull acc0 = 0, acc1 = 0;
    for (int j = 0; j < degp; j += 16) {
        ull y[16];
#pragma unroll
        for (int u = 0; u < 16; u++)           // 16 gathers in flight (MLP=16)
            y[u] = *(const ull*)(pl + ((size_t)(unsigned)ss[w][j + u] << 8));
#pragma unroll
        for (int u = 0; u < 16; u += 2) {      // 2 accumulators break RAW chain
            acc0 = ffma2(y[u],     sv[w][j + u],     acc0);
            acc1 = ffma2(y[u + 1], sv[w][j + u + 1], acc1);
        }
    }
    float2 r0 = f2_unpack(acc0), r1 = f2_unpack(acc1);
    float2 r = make_float2(r0.x + r1.x, r0.y + r1.y);
    if (WHICH == 0) { r.x = tanhf(r.x); r.y = tanhf(r.y); }
    *(float2*)(hout + ((size_t)node << 6) + (lane << 1)) = r;
}

// ---------------- SPMM 16-dim + softmax + counter re-zero (8 edges/half-warp bursts) ----------------
__global__ void spmm16_softmax_kernel(float* __restrict__ out) {
    __shared__ int   ss[8][CAP];
    __shared__ float sf[8][CAP];
    int w = threadIdx.x >> 5, lane = threadIdx.x & 31;
    int node = blockIdx.x * 8 + w;
    if (node >= NND) return;
    int deg = min(g_cnt[node], CAP);
    if (lane == 0) g_cnt[node] = 0;            // restore invariant for next replay
    int degp = (deg + 15) & ~15;
    size_t base = (size_t)node * CAP;
    for (int i = lane; i < degp; i += 32) {
        if (i < deg) {
            int2 e = g_slot[base + i];
            ss[w][i] = e.x;
            sf[w][i] = __int_as_float(e.y);
        } else {
            ss[w][i] = 0;
            sf[w][i] = 0.f;
        }
    }
    __syncwarp();
    int half = lane >> 4, dim = lane & 15;
    const float* pl = g_t3 + dim;
    float acc = 0.f;
    for (int j = 0; j < degp; j += 16) {       // 8 edges per half-warp per burst
        float y[8];
#pragma unroll
        for (int u = 0; u < 8; u++)
            y[u] = pl[(size_t)(unsigned)ss[w][j + u * 2 + half] * DOUT];
#pragma unroll
        for (int u = 0; u < 8; u++)
            acc = fmaf(sf[w][j + u * 2 + half], y[u], acc);
    }
    acc += __shfl_down_sync(0xffffffffu, acc, 16);
    float mx = acc;
#pragma unroll
    for (int o = 8; o > 0; o >>= 1)
        mx = fmaxf(mx, __shfl_xor_sync(0xffffffffu, mx, o));
    float e = expf(acc - mx);
    float s = e;
#pragma unroll
    for (int o = 8; o > 0; o >>= 1)
        s += __shfl_xor_sync(0xffffffffu, s, o);
    if (lane < DOUT)
        out[(size_t)node * DOUT + lane] = e / s;
}

// ---------------- launch (7 kernels) ----------------
extern "C" void kernel_launch(void* const* d_in, const int* in_sizes, int n_in,
                              void* d_out, int out_size) {
    const float* x    = (const float*)d_in[0];
    const int*   esrc = (const int*)  d_in[1];
    const int*   edst = (const int*)  d_in[2];
    const float* evals= (const float*)d_in[3];
    const float* W1   = (const float*)d_in[4];
    const float* W2   = (const float*)d_in[5];
    const float* W3   = (const float*)d_in[6];
    float* out = (float*)d_out;

    scatter_kernel<<<(NE + 255) / 256, 256>>>(esrc, edst, evals);
    gemm1_kernel<<<(NND + 63) / 64, 256>>>(x, W1);
    spmm64_kernel<0><<<(NND + 7) / 8, 256>>>();     // t1 = tanh(A @ h0)
    gemm2_kernel<<<(NND + 63) / 64, 256>>>(W2);     // t2 = t1 @ W2
    spmm64_kernel<1><<<(NND + 7) / 8, 256>>>();     // a2 = A @ t2
    gemm3_kernel<<<(NND + 63) / 64, 256>>>(W3);     // t3 = a2 @ W3
    spmm16_softmax_kernel<<<(NND + 7) / 8, 256>>>(out);  // softmax + cnt re-zero
}